// round 3
// baseline (speedup 1.0000x reference)
#include <cuda_runtime.h>
#include <math.h>

// ---------------- problem constants ----------------
#define TOT_N   128000      // B*N nodes
#define NEDGE   512000      // total edges
#define NB      128         // batch of graphs
#define HID     64          // H
#define NHEADS  4
#define DH      16
#define FIN     32
#define NLAYERS 4
#define AOUT    15
#define OBSD    1500
#define HSZ     512
#define VH      128
#define FEATD   (AOUT + OBSD)   // 1515
#define KC      32              // GEMM K-chunk

// ---------------- scratch (no allocs allowed) ----------------
__device__ float g_x   [TOT_N * HID];
__device__ float g_qkv [TOT_N * 3 * HID];
__device__ float g_agg [TOT_N * HID];
__device__ float g_h   [TOT_N * 2 * HID];
__device__ int   g_cnt[TOT_N];
__device__ int   g_off[TOT_N + 1];
__device__ int   g_csr[NEDGE];
__device__ float g_feat[NB * FEATD];
__device__ float g_f1 [NB * HSZ];
__device__ float g_f2 [NB * HSZ];
__device__ float g_vh [NB * VH];
__device__ float g_vh2[NB * VH];

// ---------------- CSR build ----------------
__global__ void count_kernel(const int* __restrict__ dst) {
    int e = blockIdx.x * blockDim.x + threadIdx.x;
    if (e < NEDGE) atomicAdd(&g_cnt[dst[e]], 1);
}

__global__ void scan_kernel() {
    __shared__ int ssum[1024];
    int t = threadIdx.x;
    const int chunk = (TOT_N + 1023) / 1024;
    int start = t * chunk;
    int end = start + chunk; if (end > TOT_N) end = TOT_N;
    if (start > TOT_N) start = TOT_N;
    int s = 0;
    for (int i = start; i < end; i++) s += g_cnt[i];
    ssum[t] = s;
    __syncthreads();
    for (int d = 1; d < 1024; d <<= 1) {
        int v = 0;
        if (t >= d) v = ssum[t - d];
        __syncthreads();
        if (t >= d) ssum[t] += v;
        __syncthreads();
    }
    int run = (t > 0) ? ssum[t - 1] : 0;
    for (int i = start; i < end; i++) {
        int c = g_cnt[i];
        g_off[i] = run;
        run += c;
    }
    if (end == TOT_N) g_off[TOT_N] = run;
}

__global__ void scatter_kernel(const int* __restrict__ src, const int* __restrict__ dst) {
    int e = blockIdx.x * blockDim.x + threadIdx.x;
    if (e < NEDGE) {
        int d = dst[e];
        int pos = g_off[d] + atomicAdd(&g_cnt[d], 1);
        g_csr[pos] = src[e];
    }
}

// ---------------- per-(node,head) online-softmax attention (qkv packed [n,192]) --------
__global__ void attn_kernel(const float* __restrict__ qkv, float* __restrict__ agg) {
    int idx = blockIdx.x * blockDim.x + threadIdx.x;
    if (idx >= TOT_N * NHEADS) return;
    int n = idx >> 2;
    int h = idx & 3;
    const float4* qp = (const float4*)(qkv + (size_t)n * 192 + h * DH);
    float4 q0 = qp[0], q1 = qp[1], q2 = qp[2], q3 = qp[3];
    int e0 = g_off[n], e1 = g_off[n + 1];
    float M = -3.402823e38f, D = 0.f;
    float a[16];
#pragma unroll
    for (int i = 0; i < 16; i++) a[i] = 0.f;
    for (int e = e0; e < e1; e++) {
        int s = g_csr[e];
        const float4* kp = (const float4*)(qkv + (size_t)s * 192 + 64 + h * DH);
        float4 k0 = kp[0], k1 = kp[1], k2 = kp[2], k3 = kp[3];
        float dot = q0.x*k0.x + q0.y*k0.y + q0.z*k0.z + q0.w*k0.w
                  + q1.x*k1.x + q1.y*k1.y + q1.z*k1.z + q1.w*k1.w
                  + q2.x*k2.x + q2.y*k2.y + q2.z*k2.z + q2.w*k2.w
                  + q3.x*k3.x + q3.y*k3.y + q3.z*k3.z + q3.w*k3.w;
        dot *= 0.25f;  // 1/sqrt(DH)
        float Mn = fmaxf(M, dot);
        float sc = __expf(M - Mn);
        float w  = __expf(dot - Mn);
        D = D * sc + w;
        const float4* vp = (const float4*)(qkv + (size_t)s * 192 + 128 + h * DH);
        float4 v0 = vp[0], v1 = vp[1], v2 = vp[2], v3 = vp[3];
        a[0]  = a[0]*sc  + w*v0.x;  a[1]  = a[1]*sc  + w*v0.y;
        a[2]  = a[2]*sc  + w*v0.z;  a[3]  = a[3]*sc  + w*v0.w;
        a[4]  = a[4]*sc  + w*v1.x;  a[5]  = a[5]*sc  + w*v1.y;
        a[6]  = a[6]*sc  + w*v1.z;  a[7]  = a[7]*sc  + w*v1.w;
        a[8]  = a[8]*sc  + w*v2.x;  a[9]  = a[9]*sc  + w*v2.y;
        a[10] = a[10]*sc + w*v2.z;  a[11] = a[11]*sc + w*v2.w;
        a[12] = a[12]*sc + w*v3.x;  a[13] = a[13]*sc + w*v3.y;
        a[14] = a[14]*sc + w*v3.z;  a[15] = a[15]*sc + w*v3.w;
        M = Mn;
    }
    float inv = 1.f / (D + 1e-9f);
    float4* op = (float4*)(agg + (size_t)n * HID + h * DH);
    op[0] = make_float4(a[0]*inv,  a[1]*inv,  a[2]*inv,  a[3]*inv);
    op[1] = make_float4(a[4]*inv,  a[5]*inv,  a[6]*inv,  a[7]*inv);
    op[2] = make_float4(a[8]*inv,  a[9]*inv,  a[10]*inv, a[11]*inv);
    op[3] = make_float4(a[12]*inv, a[13]*inv, a[14]*inv, a[15]*inv);
}

// ---------------- tiled GEMM: block = 128 rows x 64 cols, thread = 2 rows x 16 cols ----
// C[rowBase.., colC..colC+64) = A[rows, 0:KTOT] @ Bm[:, colB..colB+64)  (+bias)(relu)
// QKV mode: blockIdx.y selects B0/B1/B2, colB=0, colC=y*64 (ldC=192).
// LN mode (requires gridDim.y==1, N=64 full row): C = LN(resid + GEMM(+bias)) with
//   row stats reduced across the 4 lanes owning the row (shfl_xor 1,2).
// M must be a multiple of 128 (TOT_N = 128000 -> 1000 blocks, no guards).
template <int KTOT, bool RELU, bool HAS_BIAS, bool QKV, bool LN>
__global__ void __launch_bounds__(256)
gemm64(const float* __restrict__ A,
       const float* __restrict__ B0, const float* __restrict__ B1,
       const float* __restrict__ B2,
       const float* __restrict__ bias, const float* __restrict__ resid,
       const float* __restrict__ gamma, const float* __restrict__ beta,
       float* __restrict__ C, int ldA, int ldB, int ldC) {
    __shared__ float As[KC][129];   // [k][row], pad 129 -> conflict-free stage+read
    __shared__ float Bs[KC][64];    // [k][col]

    const float* Bm;
    int colB, colC;
    if (QKV) {
        Bm = (blockIdx.y == 0) ? B0 : ((blockIdx.y == 1) ? B1 : B2);
        colB = 0; colC = blockIdx.y * 64;
    } else {
        Bm = B0; colB = blockIdx.y * 64; colC = colB;
    }
    int t = threadIdx.x;
    int rowBase = blockIdx.x * 128;
    int r  = t >> 2;   // 0..63  (thread handles rows r and r+64)
    int cg = t & 3;    // col group -> cols cg*16 .. cg*16+15

    float acc0[16], acc1[16];
#pragma unroll
    for (int i = 0; i < 16; i++) { acc0[i] = 0.f; acc1[i] = 0.f; }

#pragma unroll
    for (int kb = 0; kb < KTOT; kb += KC) {
        // stage A: 128 rows x KC, stored transposed As[k][r]
#pragma unroll
        for (int i = 0; i < 4; i++) {
            int e4 = t + i * 256;          // 1024 float4 total
            int k4 = e4 & 7;               // KC/4 = 8
            int rr = e4 >> 3;              // 0..127
            float4 v = *(const float4*)(A + (size_t)(rowBase + rr) * ldA + kb + k4 * 4);
            As[k4 * 4 + 0][rr] = v.x; As[k4 * 4 + 1][rr] = v.y;
            As[k4 * 4 + 2][rr] = v.z; As[k4 * 4 + 3][rr] = v.w;
        }
        // stage B: KC x 64
#pragma unroll
        for (int i = 0; i < 2; i++) {
            int e4 = t + i * 256;          // 512 float4 total
            int kk = e4 >> 4; int nn4 = e4 & 15;
            *(float4*)&Bs[kk][nn4 * 4] =
                *(const float4*)(Bm + (size_t)(kb + kk) * ldB + colB + nn4 * 4);
        }
        __syncthreads();
#pragma unroll
        for (int kk = 0; kk < KC; kk++) {
            float a0 = As[kk][r];
            float a1 = As[kk][r + 64];
            float bv[16];
            const float4* bp = (const float4*)&Bs[kk][cg * 16];
            float4 b0 = bp[0], b1 = bp[1], b2 = bp[2], b3 = bp[3];
            bv[0]=b0.x; bv[1]=b0.y; bv[2]=b0.z; bv[3]=b0.w;
            bv[4]=b1.x; bv[5]=b1.y; bv[6]=b1.z; bv[7]=b1.w;
            bv[8]=b2.x; bv[9]=b2.y; bv[10]=b2.z; bv[11]=b2.w;
            bv[12]=b3.x; bv[13]=b3.y; bv[14]=b3.z; bv[15]=b3.w;
#pragma unroll
            for (int n = 0; n < 16; n++) {
                acc0[n] += a0 * bv[n];
                acc1[n] += a1 * bv[n];
            }
        }
        __syncthreads();
    }

    if (HAS_BIAS) {
#pragma unroll
        for (int n = 0; n < 16; n++) {
            float bb = __ldg(&bias[colB + cg * 16 + n]);
            acc0[n] += bb; acc1[n] += bb;
        }
    }
    if (RELU) {
#pragma unroll
        for (int n = 0; n < 16; n++) {
            acc0[n] = fmaxf(acc0[n], 0.f);
            acc1[n] = fmaxf(acc1[n], 0.f);
        }
    }
    if (LN) {
        // add residual (x), then LN across the full 64-wide row.
        const float4* rr0 = (const float4*)(resid + (size_t)(rowBase + r) * ldC + cg * 16);
        const float4* rr1 = (const float4*)(resid + (size_t)(rowBase + r + 64) * ldC + cg * 16);
#pragma unroll
        for (int n4 = 0; n4 < 4; n4++) {
            float4 v0 = rr0[n4], v1 = rr1[n4];
            acc0[n4*4+0] += v0.x; acc0[n4*4+1] += v0.y;
            acc0[n4*4+2] += v0.z; acc0[n4*4+3] += v0.w;
            acc1[n4*4+0] += v1.x; acc1[n4*4+1] += v1.y;
            acc1[n4*4+2] += v1.z; acc1[n4*4+3] += v1.w;
        }
        float s0 = 0.f, s1 = 0.f;
#pragma unroll
        for (int n = 0; n < 16; n++) { s0 += acc0[n]; s1 += acc1[n]; }
        s0 += __shfl_xor_sync(0xffffffffu, s0, 1);
        s0 += __shfl_xor_sync(0xffffffffu, s0, 2);
        s1 += __shfl_xor_sync(0xffffffffu, s1, 1);
        s1 += __shfl_xor_sync(0xffffffffu, s1, 2);
        float mean0 = s0 * (1.f / HID), mean1 = s1 * (1.f / HID);
        float v0 = 0.f, v1 = 0.f;
#pragma unroll
        for (int n = 0; n < 16; n++) {
            float d0 = acc0[n] - mean0; v0 += d0 * d0;
            float d1 = acc1[n] - mean1; v1 += d1 * d1;
        }
        v0 += __shfl_xor_sync(0xffffffffu, v0, 1);
        v0 += __shfl_xor_sync(0xffffffffu, v0, 2);
        v1 += __shfl_xor_sync(0xffffffffu, v1, 1);
        v1 += __shfl_xor_sync(0xffffffffu, v1, 2);
        float rs0 = rsqrtf(v0 * (1.f / HID) + 1e-5f);
        float rs1 = rsqrtf(v1 * (1.f / HID) + 1e-5f);
#pragma unroll
        for (int n = 0; n < 16; n++) {
            float gg = __ldg(&gamma[cg * 16 + n]);
            float bb = __ldg(&beta[cg * 16 + n]);
            acc0[n] = (acc0[n] - mean0) * rs0 * gg + bb;
            acc1[n] = (acc1[n] - mean1) * rs1 * gg + bb;
        }
    }
    float* c0 = C + (size_t)(rowBase + r) * ldC + colC + cg * 16;
    float* c1 = C + (size_t)(rowBase + r + 64) * ldC + colC + cg * 16;
#pragma unroll
    for (int n4 = 0; n4 < 4; n4++) {
        ((float4*)c0)[n4] = make_float4(acc0[n4*4+0], acc0[n4*4+1], acc0[n4*4+2], acc0[n4*4+3]);
        ((float4*)c1)[n4] = make_float4(acc1[n4*4+0], acc1[n4*4+1], acc1[n4*4+2], acc1[n4*4+3]);
    }
}

// ---------------- readout: gat_out into feat[:,0:15], copy obs into feat[:,15:1515] ----
__global__ void readout_kernel(const float* __restrict__ x, const int* __restrict__ agents,
                               const float* __restrict__ Wr, const float* __restrict__ br,
                               const float* __restrict__ obs, float* __restrict__ feat) {
    int row = blockIdx.x;
    __shared__ float sx[HID];
    int node = agents[row];
    if (threadIdx.x < HID) sx[threadIdx.x] = x[(size_t)node * HID + threadIdx.x];
    __syncthreads();
    if (threadIdx.x < AOUT) {
        float acc = br[threadIdx.x];
        for (int k = 0; k < HID; k++) acc += sx[k] * Wr[k * AOUT + threadIdx.x];
        feat[(size_t)row * FEATD + threadIdx.x] = acc;
    }
    for (int i = threadIdx.x; i < OBSD; i += blockDim.x)
        feat[(size_t)row * FEATD + AOUT + i] = obs[(size_t)row * OBSD + i];
}

// ---------------- small FC: one block per row ----------------
__global__ void fc_kernel(const float* __restrict__ in, int ldIn,
                          const float* __restrict__ W, const float* __restrict__ bias,
                          float* __restrict__ out, int ldOut,
                          int K, int N, int act /*1=tanh*/) {
    extern __shared__ float s_in[];
    int row = blockIdx.x;
    for (int i = threadIdx.x; i < K; i += blockDim.x)
        s_in[i] = in[(size_t)row * ldIn + i];
    __syncthreads();
    int n = threadIdx.x;
    if (n >= N) return;
    float acc = bias ? __ldg(&bias[n]) : 0.f;
    int k = 0;
    for (; k + 4 <= K; k += 4) {
        acc += s_in[k]     * W[(size_t)k       * N + n];
        acc += s_in[k + 1] * W[(size_t)(k + 1) * N + n];
        acc += s_in[k + 2] * W[(size_t)(k + 2) * N + n];
        acc += s_in[k + 3] * W[(size_t)(k + 3) * N + n];
    }
    for (; k < K; k++) acc += s_in[k] * W[(size_t)k * N + n];
    if (act) acc = tanhf(acc);
    out[(size_t)row * ldOut + n] = acc;
}

// ---------------- launch ----------------
extern "C" void kernel_launch(void* const* d_in, const int* in_sizes, int n_in,
                              void* d_out, int out_size) {
    const float* node_feats = (const float*)d_in[0];
    const float* obs        = (const float*)d_in[1];
    const int*   edge_src   = (const int*)d_in[2];
    const int*   edge_dst   = (const int*)d_in[3];
    const int*   agents     = (const int*)d_in[4];
    const float* W_in = (const float*)d_in[5];
    const float* Wq   = (const float*)d_in[6];
    const float* Wk   = (const float*)d_in[7];
    const float* Wv   = (const float*)d_in[8];
    const float* Wo   = (const float*)d_in[9];
    const float* ln1g = (const float*)d_in[10];
    const float* ln1b = (const float*)d_in[11];
    const float* W1   = (const float*)d_in[12];
    const float* b1   = (const float*)d_in[13];
    const float* W2   = (const float*)d_in[14];
    const float* b2   = (const float*)d_in[15];
    const float* ln2g = (const float*)d_in[16];
    const float* ln2b = (const float*)d_in[17];
    const float* Wr   = (const float*)d_in[18];
    const float* br   = (const float*)d_in[19];
    const float* Wp1  = (const float*)d_in[20];
    const float* bp1  = (const float*)d_in[21];
    const float* Wp2  = (const float*)d_in[22];
    const float* bp2  = (const float*)d_in[23];
    const float* Wlog = (const float*)d_in[24];
    const float* blog = (const float*)d_in[25];
    const float* Wv1  = (const float*)d_in[26];
    const float* bv1  = (const float*)d_in[27];
    const float* Wv2  = (const float*)d_in[28];
    const float* bv2  = (const float*)d_in[29];
    const float* Wvo  = (const float*)d_in[30];
    const float* bvo  = (const float*)d_in[31];
    float* out = (float*)d_out;

    float *x_p, *qkv_p, *agg_p, *h_p, *feat_p, *f1_p, *f2_p, *vh_p, *vh2_p;
    int* cnt_p;
    cudaGetSymbolAddress((void**)&x_p,   g_x);
    cudaGetSymbolAddress((void**)&qkv_p, g_qkv);
    cudaGetSymbolAddress((void**)&agg_p, g_agg);
    cudaGetSymbolAddress((void**)&h_p,   g_h);
    cudaGetSymbolAddress((void**)&feat_p, g_feat);
    cudaGetSymbolAddress((void**)&f1_p,  g_f1);
    cudaGetSymbolAddress((void**)&f2_p,  g_f2);
    cudaGetSymbolAddress((void**)&vh_p,  g_vh);
    cudaGetSymbolAddress((void**)&vh2_p, g_vh2);
    cudaGetSymbolAddress((void**)&cnt_p, g_cnt);

    const int GX = TOT_N / 128;          // 1000 row-blocks

    // CSR build
    cudaMemsetAsync(cnt_p, 0, TOT_N * sizeof(int));
    count_kernel<<<(NEDGE + 255) / 256, 256>>>(edge_dst);
    scan_kernel<<<1, 1024>>>();
    cudaMemsetAsync(cnt_p, 0, TOT_N * sizeof(int));
    scatter_kernel<<<(NEDGE + 255) / 256, 256>>>(edge_src, edge_dst);

    // input projection: x = node_feats @ W_in   (K=32)
    gemm64<FIN, false, false, false, false><<<dim3(GX, 1), 256>>>(
        node_feats, W_in, nullptr, nullptr, nullptr, nullptr, nullptr, nullptr,
        x_p, FIN, HID, HID);

    for (int l = 0; l < NLAYERS; l++) {
        const float* wq = Wq + (size_t)l * HID * HID;
        const float* wk = Wk + (size_t)l * HID * HID;
        const float* wv = Wv + (size_t)l * HID * HID;
        const float* wo = Wo + (size_t)l * HID * HID;

        // fused qkv: [n,192] = x @ [Wq|Wk|Wv]
        gemm64<HID, false, false, true, false><<<dim3(GX, 3), 256>>>(
            x_p, wq, wk, wv, nullptr, nullptr, nullptr, nullptr,
            qkv_p, HID, HID, 3 * HID);

        attn_kernel<<<(TOT_N * NHEADS + 255) / 256, 256>>>(qkv_p, agg_p);

        // x = LN(x + agg @ Wo)   [fused epilogue]
        gemm64<HID, false, false, false, true><<<dim3(GX, 1), 256>>>(
            agg_p, wo, nullptr, nullptr, nullptr, x_p,
            ln1g + l * HID, ln1b + l * HID, x_p, HID, HID, HID);

        // h = relu(x @ W1 + b1)   [N=128 -> grid.y = 2]
        gemm64<HID, true, true, false, false><<<dim3(GX, 2), 256>>>(
            x_p, W1 + (size_t)l * HID * 2 * HID, nullptr, nullptr,
            b1 + (size_t)l * 2 * HID, nullptr, nullptr, nullptr,
            h_p, HID, 2 * HID, 2 * HID);

        // x = LN(x + h @ W2 + b2)   [fused epilogue]
        gemm64<2 * HID, false, true, false, true><<<dim3(GX, 1), 256>>>(
            h_p, W2 + (size_t)l * 2 * HID * HID, nullptr, nullptr,
            b2 + (size_t)l * HID, x_p,
            ln2g + l * HID, ln2b + l * HID, x_p, 2 * HID, HID, HID);
    }

    // readout + concat with obs
    readout_kernel<<<NB, 256>>>(x_p, agents, Wr, br, obs, feat_p);

    // policy head
    fc_kernel<<<NB, HSZ, FEATD * sizeof(float)>>>(feat_p, FEATD, Wp1, bp1, f1_p, HSZ, FEATD, HSZ, 1);
    fc_kernel<<<NB, HSZ, HSZ * sizeof(float)>>>(f1_p, HSZ, Wp2, bp2, f2_p, HSZ, HSZ, HSZ, 1);
    fc_kernel<<<NB, HSZ, HSZ * sizeof(float)>>>(f2_p, HSZ, Wlog, blog, out, AOUT, HSZ, AOUT, 0);

    // value head
    fc_kernel<<<NB, 256, OBSD * sizeof(float)>>>(obs, OBSD, Wv1, bv1, vh_p, VH, OBSD, VH, 1);
    fc_kernel<<<NB, VH, VH * sizeof(float)>>>(vh_p, VH, Wv2, bv2, vh2_p, VH, VH, VH, 1);
    fc_kernel<<<NB, 32, VH * sizeof(float)>>>(vh2_p, VH, Wvo, bvo, out + NB * AOUT, 1, VH, 1, 0);
}

// round 6
// speedup vs baseline: 1.7589x; 1.7589x over previous
#include <cuda_runtime.h>
#include <math.h>

// ---------------- problem constants ----------------
#define TOT_N   128000      // B*N nodes
#define NEDGE   512000      // total edges
#define NB      128         // batch of graphs
#define HID     64          // H
#define NHEADS  4
#define DH      16
#define FIN     32
#define NLAYERS 4
#define AOUT    15
#define OBSD    1500
#define HSZ     512
#define VH      128
#define FEATD   (AOUT + OBSD)   // 1515
#define KC      32              // GEMM K-chunk

// ---------------- scratch (no allocs allowed) ----------------
__device__ float g_x   [TOT_N * HID];
__device__ float g_qkv [TOT_N * 3 * HID];
__device__ float g_agg [TOT_N * HID];
__device__ float g_h   [TOT_N * 2 * HID];
__device__ int   g_cnt[TOT_N];
__device__ int   g_off[TOT_N + 1];
__device__ int   g_csr[NEDGE];
__device__ float g_feat[NB * FEATD];
__device__ float g_f1 [NB * HSZ];
__device__ float g_f2 [NB * HSZ];
__device__ float g_vh [NB * VH];
__device__ float g_vh2[NB * VH];

// ---------------- CSR build ----------------
__global__ void count_kernel(const int* __restrict__ dst) {
    int e = blockIdx.x * blockDim.x + threadIdx.x;
    if (e < NEDGE) atomicAdd(&g_cnt[dst[e]], 1);
}

__global__ void scan_kernel() {
    __shared__ int ssum[1024];
    int t = threadIdx.x;
    const int chunk = (TOT_N + 1023) / 1024;
    int start = t * chunk;
    int end = start + chunk; if (end > TOT_N) end = TOT_N;
    if (start > TOT_N) start = TOT_N;
    int s = 0;
    for (int i = start; i < end; i++) s += g_cnt[i];
    ssum[t] = s;
    __syncthreads();
    for (int d = 1; d < 1024; d <<= 1) {
        int v = 0;
        if (t >= d) v = ssum[t - d];
        __syncthreads();
        if (t >= d) ssum[t] += v;
        __syncthreads();
    }
    int run = (t > 0) ? ssum[t - 1] : 0;
    for (int i = start; i < end; i++) {
        int c = g_cnt[i];
        g_off[i] = run;
        run += c;
    }
    if (end == TOT_N) g_off[TOT_N] = run;
}

__global__ void scatter_kernel(const int* __restrict__ src, const int* __restrict__ dst) {
    int e = blockIdx.x * blockDim.x + threadIdx.x;
    if (e < NEDGE) {
        int d = dst[e];
        int pos = g_off[d] + atomicAdd(&g_cnt[d], 1);
        g_csr[pos] = src[e];
    }
}

// ---------------- per-(node,head) online-softmax attention (qkv packed [n,192]) --------
__global__ void attn_kernel(const float* __restrict__ qkv, float* __restrict__ agg) {
    int idx = blockIdx.x * blockDim.x + threadIdx.x;
    if (idx >= TOT_N * NHEADS) return;
    int n = idx >> 2;
    int h = idx & 3;
    const float4* qp = (const float4*)(qkv + (size_t)n * 192 + h * DH);
    float4 q0 = qp[0], q1 = qp[1], q2 = qp[2], q3 = qp[3];
    int e0 = g_off[n], e1 = g_off[n + 1];
    float M = -3.402823e38f, D = 0.f;
    float a[16];
#pragma unroll
    for (int i = 0; i < 16; i++) a[i] = 0.f;
    for (int e = e0; e < e1; e++) {
        int s = g_csr[e];
        const float4* kp = (const float4*)(qkv + (size_t)s * 192 + 64 + h * DH);
        float4 k0 = kp[0], k1 = kp[1], k2 = kp[2], k3 = kp[3];
        float dot = q0.x*k0.x + q0.y*k0.y + q0.z*k0.z + q0.w*k0.w
                  + q1.x*k1.x + q1.y*k1.y + q1.z*k1.z + q1.w*k1.w
                  + q2.x*k2.x + q2.y*k2.y + q2.z*k2.z + q2.w*k2.w
                  + q3.x*k3.x + q3.y*k3.y + q3.z*k3.z + q3.w*k3.w;
        dot *= 0.25f;  // 1/sqrt(DH)
        float Mn = fmaxf(M, dot);
        float sc = __expf(M - Mn);
        float w  = __expf(dot - Mn);
        D = D * sc + w;
        const float4* vp = (const float4*)(qkv + (size_t)s * 192 + 128 + h * DH);
        float4 v0 = vp[0], v1 = vp[1], v2 = vp[2], v3 = vp[3];
        a[0]  = a[0]*sc  + w*v0.x;  a[1]  = a[1]*sc  + w*v0.y;
        a[2]  = a[2]*sc  + w*v0.z;  a[3]  = a[3]*sc  + w*v0.w;
        a[4]  = a[4]*sc  + w*v1.x;  a[5]  = a[5]*sc  + w*v1.y;
        a[6]  = a[6]*sc  + w*v1.z;  a[7]  = a[7]*sc  + w*v1.w;
        a[8]  = a[8]*sc  + w*v2.x;  a[9]  = a[9]*sc  + w*v2.y;
        a[10] = a[10]*sc + w*v2.z;  a[11] = a[11]*sc + w*v2.w;
        a[12] = a[12]*sc + w*v3.x;  a[13] = a[13]*sc + w*v3.y;
        a[14] = a[14]*sc + w*v3.z;  a[15] = a[15]*sc + w*v3.w;
        M = Mn;
    }
    float inv = 1.f / (D + 1e-9f);
    float4* op = (float4*)(agg + (size_t)n * HID + h * DH);
    op[0] = make_float4(a[0]*inv,  a[1]*inv,  a[2]*inv,  a[3]*inv);
    op[1] = make_float4(a[4]*inv,  a[5]*inv,  a[6]*inv,  a[7]*inv);
    op[2] = make_float4(a[8]*inv,  a[9]*inv,  a[10]*inv, a[11]*inv);
    op[3] = make_float4(a[12]*inv, a[13]*inv, a[14]*inv, a[15]*inv);
}

// ---------------- tiled GEMM v3: block = 128 x 64, thread = 8 rows x 4 cols ------------
// Software-pipelined fragments (kk+1 loaded before kk's FFMAs).
// QKV mode: blockIdx.y selects B0/B1/B2, colB=0, colC=y*64 (ldC=192).
// LN mode (gridDim.y==1): C = LN(resid + GEMM(+bias)); row stats via 16-lane shuffles.
// M multiple of 128, KTOT multiple of KC.
template <int KTOT, bool RELU, bool HAS_BIAS, bool QKV, bool LN>
__global__ void __launch_bounds__(256)
gemmT(const float* __restrict__ A,
      const float* __restrict__ B0, const float* __restrict__ B1,
      const float* __restrict__ B2,
      const float* __restrict__ bias, const float* __restrict__ resid,
      const float* __restrict__ gamma, const float* __restrict__ beta,
      float* __restrict__ C, int ldA, int ldB, int ldC) {
    __shared__ float As[KC][132];   // [k][row]; 132 keeps float4 alignment (132%4==0)
    __shared__ float Bs[KC][64];    // [k][col]

    const float* Bm;
    int colB, colC;
    if (QKV) {
        Bm = (blockIdx.y == 0) ? B0 : ((blockIdx.y == 1) ? B1 : B2);
        colB = 0; colC = blockIdx.y * 64;
    } else {
        Bm = B0; colB = blockIdx.y * 64; colC = colB;
    }
    int t = threadIdx.x;
    int rowBase = blockIdx.x * 128;
    int tx = t & 15;          // col group: cols tx*4 .. tx*4+3
    int ty = t >> 4;          // row group: rows ty*8 .. ty*8+7

    float acc[8][4];
#pragma unroll
    for (int i = 0; i < 8; i++)
#pragma unroll
        for (int j = 0; j < 4; j++) acc[i][j] = 0.f;

#pragma unroll
    for (int kb = 0; kb < KTOT; kb += KC) {
        // stage A: 128 rows x KC, transposed As[k][row].
        // index so that rr varies fastest across lanes -> conflict-free scalar stores.
#pragma unroll
        for (int i = 0; i < 4; i++) {
            int e4 = t + i * 256;          // 1024 float4 total
            int rr = e4 & 127;             // row 0..127 (varies across lanes)
            int k4 = e4 >> 7;              // 0..7  (KC/4)
            float4 v = *(const float4*)(A + (size_t)(rowBase + rr) * ldA + kb + k4 * 4);
            As[k4 * 4 + 0][rr] = v.x; As[k4 * 4 + 1][rr] = v.y;
            As[k4 * 4 + 2][rr] = v.z; As[k4 * 4 + 3][rr] = v.w;
        }
        // stage B: KC x 64
#pragma unroll
        for (int i = 0; i < 2; i++) {
            int e4 = t + i * 256;          // 512 float4 total
            int kk = e4 >> 4; int nn4 = e4 & 15;
            *(float4*)&Bs[kk][nn4 * 4] =
                *(const float4*)(Bm + (size_t)(kb + kk) * ldB + colB + nn4 * 4);
        }
        __syncthreads();

        // software-pipelined inner loop
        float4 fa0 = *(const float4*)&As[0][ty * 8];
        float4 fa1 = *(const float4*)&As[0][ty * 8 + 4];
        float4 fb  = *(const float4*)&Bs[0][tx * 4];
#pragma unroll
        for (int kk = 0; kk < KC; kk++) {
            int nk = (kk + 1 < KC) ? (kk + 1) : kk;
            float4 na0 = *(const float4*)&As[nk][ty * 8];
            float4 na1 = *(const float4*)&As[nk][ty * 8 + 4];
            float4 nb  = *(const float4*)&Bs[nk][tx * 4];
            float a8[8] = {fa0.x, fa0.y, fa0.z, fa0.w, fa1.x, fa1.y, fa1.z, fa1.w};
            float b4[4] = {fb.x, fb.y, fb.z, fb.w};
#pragma unroll
            for (int i = 0; i < 8; i++)
#pragma unroll
                for (int j = 0; j < 4; j++)
                    acc[i][j] += a8[i] * b4[j];
            fa0 = na0; fa1 = na1; fb = nb;
        }
        __syncthreads();
    }

    int row0 = rowBase + ty * 8;
    if (HAS_BIAS) {
        float bb[4];
#pragma unroll
        for (int j = 0; j < 4; j++) bb[j] = __ldg(&bias[colB + tx * 4 + j]);
#pragma unroll
        for (int i = 0; i < 8; i++)
#pragma unroll
            for (int j = 0; j < 4; j++) acc[i][j] += bb[j];
    }
    if (RELU) {
#pragma unroll
        for (int i = 0; i < 8; i++)
#pragma unroll
            for (int j = 0; j < 4; j++) acc[i][j] = fmaxf(acc[i][j], 0.f);
    }
    if (LN) {
        // add residual
#pragma unroll
        for (int i = 0; i < 8; i++) {
            float4 rv = *(const float4*)(resid + (size_t)(row0 + i) * ldC + tx * 4);
            acc[i][0] += rv.x; acc[i][1] += rv.y; acc[i][2] += rv.z; acc[i][3] += rv.w;
        }
        // row sums, reduced over the 16 lanes (same ty) — contiguous half-warp
        float s[8];
#pragma unroll
        for (int i = 0; i < 8; i++) s[i] = acc[i][0] + acc[i][1] + acc[i][2] + acc[i][3];
#pragma unroll
        for (int o = 1; o < 16; o <<= 1)
#pragma unroll
            for (int i = 0; i < 8; i++) s[i] += __shfl_xor_sync(0xffffffffu, s[i], o);
        float mean[8];
#pragma unroll
        for (int i = 0; i < 8; i++) mean[i] = s[i] * (1.f / HID);
        float v[8];
#pragma unroll
        for (int i = 0; i < 8; i++) {
            float d0 = acc[i][0] - mean[i], d1 = acc[i][1] - mean[i];
            float d2 = acc[i][2] - mean[i], d3 = acc[i][3] - mean[i];
            v[i] = d0 * d0 + d1 * d1 + d2 * d2 + d3 * d3;
        }
#pragma unroll
        for (int o = 1; o < 16; o <<= 1)
#pragma unroll
            for (int i = 0; i < 8; i++) v[i] += __shfl_xor_sync(0xffffffffu, v[i], o);
        float gg[4], bb2[4];
#pragma unroll
        for (int j = 0; j < 4; j++) {
            gg[j]  = __ldg(&gamma[tx * 4 + j]);
            bb2[j] = __ldg(&beta[tx * 4 + j]);
        }
#pragma unroll
        for (int i = 0; i < 8; i++) {
            float rs = rsqrtf(v[i] * (1.f / HID) + 1e-5f);
#pragma unroll
            for (int j = 0; j < 4; j++)
                acc[i][j] = (acc[i][j] - mean[i]) * rs * gg[j] + bb2[j];
        }
    }
#pragma unroll
    for (int i = 0; i < 8; i++) {
        *(float4*)(C + (size_t)(row0 + i) * ldC + colC + tx * 4) =
            make_float4(acc[i][0], acc[i][1], acc[i][2], acc[i][3]);
    }
}

// ---------------- readout: gat_out into feat[:,0:15], copy obs into feat[:,15:1515] ----
__global__ void readout_kernel(const float* __restrict__ x, const int* __restrict__ agents,
                               const float* __restrict__ Wr, const float* __restrict__ br,
                               const float* __restrict__ obs, float* __restrict__ feat) {
    int row = blockIdx.x;
    __shared__ float sx[HID];
    int node = agents[row];
    if (threadIdx.x < HID) sx[threadIdx.x] = x[(size_t)node * HID + threadIdx.x];
    __syncthreads();
    if (threadIdx.x < AOUT) {
        float acc = br[threadIdx.x];
        for (int k = 0; k < HID; k++) acc += sx[k] * Wr[k * AOUT + threadIdx.x];
        feat[(size_t)row * FEATD + threadIdx.x] = acc;
    }
    for (int i = threadIdx.x; i < OBSD; i += blockDim.x)
        feat[(size_t)row * FEATD + AOUT + i] = obs[(size_t)row * OBSD + i];
}

// ---------------- small FC: one block per row ----------------
__global__ void fc_kernel(const float* __restrict__ in, int ldIn,
                          const float* __restrict__ W, const float* __restrict__ bias,
                          float* __restrict__ out, int ldOut,
                          int K, int N, int act /*1=tanh*/) {
    extern __shared__ float s_in[];
    int row = blockIdx.x;
    for (int i = threadIdx.x; i < K; i += blockDim.x)
        s_in[i] = in[(size_t)row * ldIn + i];
    __syncthreads();
    int n = threadIdx.x;
    if (n >= N) return;
    float acc = bias ? __ldg(&bias[n]) : 0.f;
    int k = 0;
    for (; k + 4 <= K; k += 4) {
        acc += s_in[k]     * W[(size_t)k       * N + n];
        acc += s_in[k + 1] * W[(size_t)(k + 1) * N + n];
        acc += s_in[k + 2] * W[(size_t)(k + 2) * N + n];
        acc += s_in[k + 3] * W[(size_t)(k + 3) * N + n];
    }
    for (; k < K; k++) acc += s_in[k] * W[(size_t)k * N + n];
    if (act) acc = tanhf(acc);
    out[(size_t)row * ldOut + n] = acc;
}

// ---------------- launch ----------------
extern "C" void kernel_launch(void* const* d_in, const int* in_sizes, int n_in,
                              void* d_out, int out_size) {
    const float* node_feats = (const float*)d_in[0];
    const float* obs        = (const float*)d_in[1];
    const int*   edge_src   = (const int*)d_in[2];
    const int*   edge_dst   = (const int*)d_in[3];
    const int*   agents     = (const int*)d_in[4];
    const float* W_in = (const float*)d_in[5];
    const float* Wq   = (const float*)d_in[6];
    const float* Wk   = (const float*)d_in[7];
    const float* Wv   = (const float*)d_in[8];
    const float* Wo   = (const float*)d_in[9];
    const float* ln1g = (const float*)d_in[10];
    const float* ln1b = (const float*)d_in[11];
    const float* W1   = (const float*)d_in[12];
    const float* b1   = (const float*)d_in[13];
    const float* W2   = (const float*)d_in[14];
    const float* b2   = (const float*)d_in[15];
    const float* ln2g = (const float*)d_in[16];
    const float* ln2b = (const float*)d_in[17];
    const float* Wr   = (const float*)d_in[18];
    const float* br   = (const float*)d_in[19];
    const float* Wp1  = (const float*)d_in[20];
    const float* bp1  = (const float*)d_in[21];
    const float* Wp2  = (const float*)d_in[22];
    const float* bp2  = (const float*)d_in[23];
    const float* Wlog = (const float*)d_in[24];
    const float* blog = (const float*)d_in[25];
    const float* Wv1  = (const float*)d_in[26];
    const float* bv1  = (const float*)d_in[27];
    const float* Wv2  = (const float*)d_in[28];
    const float* bv2  = (const float*)d_in[29];
    const float* Wvo  = (const float*)d_in[30];
    const float* bvo  = (const float*)d_in[31];
    float* out = (float*)d_out;

    float *x_p, *qkv_p, *agg_p, *h_p, *feat_p, *f1_p, *f2_p, *vh_p, *vh2_p;
    int* cnt_p;
    cudaGetSymbolAddress((void**)&x_p,   g_x);
    cudaGetSymbolAddress((void**)&qkv_p, g_qkv);
    cudaGetSymbolAddress((void**)&agg_p, g_agg);
    cudaGetSymbolAddress((void**)&h_p,   g_h);
    cudaGetSymbolAddress((void**)&feat_p, g_feat);
    cudaGetSymbolAddress((void**)&f1_p,  g_f1);
    cudaGetSymbolAddress((void**)&f2_p,  g_f2);
    cudaGetSymbolAddress((void**)&vh_p,  g_vh);
    cudaGetSymbolAddress((void**)&vh2_p, g_vh2);
    cudaGetSymbolAddress((void**)&cnt_p, g_cnt);

    const int GX = TOT_N / 128;          // 1000 row-blocks

    // CSR build
    cudaMemsetAsync(cnt_p, 0, TOT_N * sizeof(int));
    count_kernel<<<(NEDGE + 255) / 256, 256>>>(edge_dst);
    scan_kernel<<<1, 1024>>>();
    cudaMemsetAsync(cnt_p, 0, TOT_N * sizeof(int));
    scatter_kernel<<<(NEDGE + 255) / 256, 256>>>(edge_src, edge_dst);

    // input projection: x = node_feats @ W_in   (K=32)
    gemmT<FIN, false, false, false, false><<<dim3(GX, 1), 256>>>(
        node_feats, W_in, nullptr, nullptr, nullptr, nullptr, nullptr, nullptr,
        x_p, FIN, HID, HID);

    for (int l = 0; l < NLAYERS; l++) {
        const float* wq = Wq + (size_t)l * HID * HID;
        const float* wk = Wk + (size_t)l * HID * HID;
        const float* wv = Wv + (size_t)l * HID * HID;
        const float* wo = Wo + (size_t)l * HID * HID;

        // fused qkv: [n,192] = x @ [Wq|Wk|Wv]
        gemmT<HID, false, false, true, false><<<dim3(GX, 3), 256>>>(
            x_p, wq, wk, wv, nullptr, nullptr, nullptr, nullptr,
            qkv_p, HID, HID, 3 * HID);

        attn_kernel<<<(TOT_N * NHEADS + 255) / 256, 256>>>(qkv_p, agg_p);

        // x = LN(x + agg @ Wo)   [fused epilogue]
        gemmT<HID, false, false, false, true><<<dim3(GX, 1), 256>>>(
            agg_p, wo, nullptr, nullptr, nullptr, x_p,
            ln1g + l * HID, ln1b + l * HID, x_p, HID, HID, HID);

        // h = relu(x @ W1 + b1)   [N=128 -> grid.y = 2]
        gemmT<HID, true, true, false, false><<<dim3(GX, 2), 256>>>(
            x_p, W1 + (size_t)l * HID * 2 * HID, nullptr, nullptr,
            b1 + (size_t)l * 2 * HID, nullptr, nullptr, nullptr,
            h_p, HID, 2 * HID, 2 * HID);

        // x = LN(x + h @ W2 + b2)   [fused epilogue]
        gemmT<2 * HID, false, true, false, true><<<dim3(GX, 1), 256>>>(
            h_p, W2 + (size_t)l * 2 * HID * HID, nullptr, nullptr,
            b2 + (size_t)l * HID, x_p,
            ln2g + l * HID, ln2b + l * HID, x_p, 2 * HID, HID, HID);
    }

    // readout + concat with obs
    readout_kernel<<<NB, 256>>>(x_p, agents, Wr, br, obs, feat_p);

    // policy head
    fc_kernel<<<NB, HSZ, FEATD * sizeof(float)>>>(feat_p, FEATD, Wp1, bp1, f1_p, HSZ, FEATD, HSZ, 1);
    fc_kernel<<<NB, HSZ, HSZ * sizeof(float)>>>(f1_p, HSZ, Wp2, bp2, f2_p, HSZ, HSZ, HSZ, 1);
    fc_kernel<<<NB, HSZ, HSZ * sizeof(float)>>>(f2_p, HSZ, Wlog, blog, out, AOUT, HSZ, AOUT, 0);

    // value head
    fc_kernel<<<NB, 256, OBSD * sizeof(float)>>>(obs, OBSD, Wv1, bv1, vh_p, VH, OBSD, VH, 1);
    fc_kernel<<<NB, VH, VH * sizeof(float)>>>(vh_p, VH, Wv2, bv2, vh2_p, VH, VH, VH, 1);
    fc_kernel<<<NB, 32, VH * sizeof(float)>>>(vh2_p, VH, Wvo, bvo, out + NB * AOUT, 1, VH, 1, 0);
}

// round 7
// speedup vs baseline: 1.7680x; 1.0052x over previous
#include <cuda_runtime.h>
#include <math.h>
#include <stdint.h>

// ---------------- problem constants ----------------
#define TOT_N   128000      // B*N nodes
#define NEDGE   512000      // total edges
#define NB      128         // batch of graphs
#define HID     64          // H
#define NHEADS  4
#define DH      16
#define FIN     32
#define NLAYERS 4
#define AOUT    15
#define OBSD    1500
#define HSZ     512
#define VH      128
#define FEATD   (AOUT + OBSD)   // 1515
#define KC      32              // GEMM K-chunk

// weight-split scratch offsets (floats)
#define OFF_WIN 0
#define SZ_WIN  (FIN * HID)                       // 2048
#define OFF_WQ  (OFF_WIN + SZ_WIN)
#define SZ_W    (NLAYERS * HID * HID)             // 16384
#define OFF_WK  (OFF_WQ + SZ_W)
#define OFF_WV  (OFF_WK + SZ_W)
#define OFF_WO  (OFF_WV + SZ_W)
#define OFF_W1  (OFF_WO + SZ_W)
#define SZ_W1   (NLAYERS * HID * 2 * HID)         // 32768
#define OFF_W2  (OFF_W1 + SZ_W1)
#define SZ_W2   (NLAYERS * 2 * HID * HID)         // 32768
#define WSPLIT_TOT (OFF_W2 + SZ_W2)               // 133120

// ---------------- scratch (no allocs allowed) ----------------
__device__ float g_x   [TOT_N * HID];
__device__ float g_qkv [TOT_N * 3 * HID];
__device__ float g_agg [TOT_N * HID];
__device__ float g_h   [TOT_N * 2 * HID];
__device__ float g_whi [WSPLIT_TOT];
__device__ float g_wlo [WSPLIT_TOT];
__device__ int   g_cnt[TOT_N];
__device__ int   g_off[TOT_N + 1];
__device__ int   g_csr[NEDGE];
__device__ float g_feat[NB * FEATD];
__device__ float g_f1 [NB * HSZ];
__device__ float g_f2 [NB * HSZ];
__device__ float g_vh [NB * VH];
__device__ float g_vh2[NB * VH];

// ---------------- tf32 helpers ----------------
__device__ __forceinline__ uint32_t f2tf(float x) {
    uint32_t r;
    asm("cvt.rna.tf32.f32 %0, %1;" : "=r"(r) : "f"(x));
    return r;
}

#define MMA_TF32(c, a, b0v, b1v) \
    asm volatile("mma.sync.aligned.m16n8k8.row.col.f32.tf32.tf32.f32 " \
        "{%0,%1,%2,%3}, {%4,%5,%6,%7}, {%8,%9}, {%0,%1,%2,%3};" \
        : "+f"((c)[0]), "+f"((c)[1]), "+f"((c)[2]), "+f"((c)[3]) \
        : "r"((a)[0]), "r"((a)[1]), "r"((a)[2]), "r"((a)[3]), "r"(b0v), "r"(b1v))

// ---------------- weight hi/lo split (once per launch) ----------------
__global__ void split_kernel(const float* __restrict__ src, float* __restrict__ hi,
                             float* __restrict__ lo, int n) {
    int i = blockIdx.x * 256 + threadIdx.x;
    if (i < n) {
        float x  = src[i];
        float hf = __uint_as_float(f2tf(x));
        hi[i] = hf;
        lo[i] = __uint_as_float(f2tf(x - hf));
    }
}

// ---------------- CSR build ----------------
__global__ void count_kernel(const int* __restrict__ dst) {
    int e = blockIdx.x * blockDim.x + threadIdx.x;
    if (e < NEDGE) atomicAdd(&g_cnt[dst[e]], 1);
}

__global__ void scan_kernel() {
    __shared__ int ssum[1024];
    int t = threadIdx.x;
    const int chunk = (TOT_N + 1023) / 1024;
    int start = t * chunk;
    int end = start + chunk; if (end > TOT_N) end = TOT_N;
    if (start > TOT_N) start = TOT_N;
    int s = 0;
    for (int i = start; i < end; i++) s += g_cnt[i];
    ssum[t] = s;
    __syncthreads();
    for (int d = 1; d < 1024; d <<= 1) {
        int v = 0;
        if (t >= d) v = ssum[t - d];
        __syncthreads();
        if (t >= d) ssum[t] += v;
        __syncthreads();
    }
    int run = (t > 0) ? ssum[t - 1] : 0;
    for (int i = start; i < end; i++) {
        int c = g_cnt[i];
        g_off[i] = run;
        run += c;
    }
    if (end == TOT_N) g_off[TOT_N] = run;
}

__global__ void scatter_kernel(const int* __restrict__ src, const int* __restrict__ dst) {
    int e = blockIdx.x * blockDim.x + threadIdx.x;
    if (e < NEDGE) {
        int d = dst[e];
        int pos = g_off[d] + atomicAdd(&g_cnt[d], 1);
        g_csr[pos] = src[e];
    }
}

// ---------------- per-(node,head) online-softmax attention (qkv packed [n,192]) --------
__global__ void attn_kernel(const float* __restrict__ qkv, float* __restrict__ agg) {
    int idx = blockIdx.x * blockDim.x + threadIdx.x;
    if (idx >= TOT_N * NHEADS) return;
    int n = idx >> 2;
    int h = idx & 3;
    const float4* qp = (const float4*)(qkv + (size_t)n * 192 + h * DH);
    float4 q0 = qp[0], q1 = qp[1], q2 = qp[2], q3 = qp[3];
    int e0 = g_off[n], e1 = g_off[n + 1];
    float M = -3.402823e38f, D = 0.f;
    float a[16];
#pragma unroll
    for (int i = 0; i < 16; i++) a[i] = 0.f;
    for (int e = e0; e < e1; e++) {
        int s = g_csr[e];
        const float4* kp = (const float4*)(qkv + (size_t)s * 192 + 64 + h * DH);
        float4 k0 = kp[0], k1 = kp[1], k2 = kp[2], k3 = kp[3];
        float dot = q0.x*k0.x + q0.y*k0.y + q0.z*k0.z + q0.w*k0.w
                  + q1.x*k1.x + q1.y*k1.y + q1.z*k1.z + q1.w*k1.w
                  + q2.x*k2.x + q2.y*k2.y + q2.z*k2.z + q2.w*k2.w
                  + q3.x*k3.x + q3.y*k3.y + q3.z*k3.z + q3.w*k3.w;
        dot *= 0.25f;  // 1/sqrt(DH)
        float Mn = fmaxf(M, dot);
        float sc = __expf(M - Mn);
        float w  = __expf(dot - Mn);
        D = D * sc + w;
        const float4* vp = (const float4*)(qkv + (size_t)s * 192 + 128 + h * DH);
        float4 v0 = vp[0], v1 = vp[1], v2 = vp[2], v3 = vp[3];
        a[0]  = a[0]*sc  + w*v0.x;  a[1]  = a[1]*sc  + w*v0.y;
        a[2]  = a[2]*sc  + w*v0.z;  a[3]  = a[3]*sc  + w*v0.w;
        a[4]  = a[4]*sc  + w*v1.x;  a[5]  = a[5]*sc  + w*v1.y;
        a[6]  = a[6]*sc  + w*v1.z;  a[7]  = a[7]*sc  + w*v1.w;
        a[8]  = a[8]*sc  + w*v2.x;  a[9]  = a[9]*sc  + w*v2.y;
        a[10] = a[10]*sc + w*v2.z;  a[11] = a[11]*sc + w*v2.w;
        a[12] = a[12]*sc + w*v3.x;  a[13] = a[13]*sc + w*v3.y;
        a[14] = a[14]*sc + w*v3.z;  a[15] = a[15]*sc + w*v3.w;
        M = Mn;
    }
    float inv = 1.f / (D + 1e-9f);
    float4* op = (float4*)(agg + (size_t)n * HID + h * DH);
    op[0] = make_float4(a[0]*inv,  a[1]*inv,  a[2]*inv,  a[3]*inv);
    op[1] = make_float4(a[4]*inv,  a[5]*inv,  a[6]*inv,  a[7]*inv);
    op[2] = make_float4(a[8]*inv,  a[9]*inv,  a[10]*inv, a[11]*inv);
    op[3] = make_float4(a[12]*inv, a[13]*inv, a[14]*inv, a[15]*inv);
}

// ---------------- tensor-core GEMM: 3xTF32 mma.sync, block = 128 x 64 -----------------
// 8 warps; warp w -> rows 16w..16w+15, all 64 cols (8 n8-tiles).
// A (f32) staged transposed As[k][row], split to tf32 hi/lo in registers.
// B pre-split hi/lo in global scratch, staged to smem.
// QKV mode: blockIdx.y selects (bh,bl) pair 0/1/2; colB=0; colC=y*64 (ldC=192).
// LN mode (gridDim.y==1): C = LN(resid + GEMM(+bias)); row owned by lanes 4*gr..4*gr+3.
template <int KTOT, bool RELU, bool HAS_BIAS, bool QKV, bool LN>
__global__ void __launch_bounds__(256)
gemmMMA(const float* __restrict__ A,
        const float* __restrict__ bh0, const float* __restrict__ bl0,
        const float* __restrict__ bh1, const float* __restrict__ bl1,
        const float* __restrict__ bh2, const float* __restrict__ bl2,
        const float* __restrict__ bias, const float* __restrict__ resid,
        const float* __restrict__ gamma, const float* __restrict__ beta,
        float* __restrict__ C, int ldA, int ldB, int ldC) {
    __shared__ float As[KC][136];   // pad 136: frag bank = 8*gc+gr -> conflict-free
    __shared__ float Bh[KC][72];    // pad 72:  frag bank = 8*gc+gr+8nt -> conflict-free
    __shared__ float Bl[KC][72];

    const float *bhp, *blp;
    int colB, colC;
    if (QKV) {
        bhp = (blockIdx.y == 0) ? bh0 : ((blockIdx.y == 1) ? bh1 : bh2);
        blp = (blockIdx.y == 0) ? bl0 : ((blockIdx.y == 1) ? bl1 : bl2);
        colB = 0; colC = blockIdx.y * 64;
    } else {
        bhp = bh0; blp = bl0;
        colB = blockIdx.y * 64; colC = colB;
    }
    int t = threadIdx.x;
    int rowBase = blockIdx.x * 128;
    int w  = t >> 5;          // warp 0..7
    int gr = (t & 31) >> 2;   // group id 0..7
    int gc = t & 3;           // thread-in-group 0..3
    int rw = w * 16;          // warp row offset in tile

    float acc[8][4];
#pragma unroll
    for (int i = 0; i < 8; i++)
#pragma unroll
        for (int j = 0; j < 4; j++) acc[i][j] = 0.f;

    for (int kb = 0; kb < KTOT; kb += KC) {
        // stage A: 128 rows x KC, transposed As[k][row]
#pragma unroll
        for (int i = 0; i < 4; i++) {
            int e4 = t + i * 256;
            int rr = e4 & 127;
            int k4 = e4 >> 7;
            float4 v = *(const float4*)(A + (size_t)(rowBase + rr) * ldA + kb + k4 * 4);
            As[k4 * 4 + 0][rr] = v.x; As[k4 * 4 + 1][rr] = v.y;
            As[k4 * 4 + 2][rr] = v.z; As[k4 * 4 + 3][rr] = v.w;
        }
        // stage B hi/lo: KC x 64 each
#pragma unroll
        for (int i = 0; i < 2; i++) {
            int e4 = t + i * 256;
            int kk = e4 >> 4; int nn4 = e4 & 15;
            size_t gidx = (size_t)(kb + kk) * ldB + colB + nn4 * 4;
            *(float4*)&Bh[kk][nn4 * 4] = *(const float4*)(bhp + gidx);
            *(float4*)&Bl[kk][nn4 * 4] = *(const float4*)(blp + gidx);
        }
        __syncthreads();

#pragma unroll
        for (int k8 = 0; k8 < KC / 8; k8++) {
            int k0 = k8 * 8;
            // A fragment (m16k8, row major)
            float af[4];
            af[0] = As[k0 + gc]    [rw + gr];
            af[1] = As[k0 + gc]    [rw + gr + 8];
            af[2] = As[k0 + gc + 4][rw + gr];
            af[3] = As[k0 + gc + 4][rw + gr + 8];
            uint32_t ah[4], al[4];
#pragma unroll
            for (int i = 0; i < 4; i++) {
                ah[i] = f2tf(af[i]);
                al[i] = f2tf(af[i] - __uint_as_float(ah[i]));
            }
#pragma unroll
            for (int nt = 0; nt < 8; nt++) {
                int n0 = nt * 8;
                uint32_t bh0v = __float_as_uint(Bh[k0 + gc]    [n0 + gr]);
                uint32_t bh1v = __float_as_uint(Bh[k0 + gc + 4][n0 + gr]);
                uint32_t bl0v = __float_as_uint(Bl[k0 + gc]    [n0 + gr]);
                uint32_t bl1v = __float_as_uint(Bl[k0 + gc + 4][n0 + gr]);
                MMA_TF32(acc[nt], ah, bh0v, bh1v);
                MMA_TF32(acc[nt], ah, bl0v, bl1v);
                MMA_TF32(acc[nt], al, bh0v, bh1v);
            }
        }
        __syncthreads();
    }

    // epilogue: thread owns rows r0 = rowBase+rw+gr, r1 = r0+8;
    // cols per ntile: 8nt + 2gc (+1). acc[nt] = {r0c0, r0c1, r1c0, r1c1}.
    int r0 = rowBase + rw + gr;
    int r1 = r0 + 8;
    if (HAS_BIAS) {
#pragma unroll
        for (int nt = 0; nt < 8; nt++) {
            float b0 = __ldg(&bias[colB + nt * 8 + 2 * gc]);
            float b1 = __ldg(&bias[colB + nt * 8 + 2 * gc + 1]);
            acc[nt][0] += b0; acc[nt][1] += b1;
            acc[nt][2] += b0; acc[nt][3] += b1;
        }
    }
    if (RELU) {
#pragma unroll
        for (int nt = 0; nt < 8; nt++)
#pragma unroll
            for (int j = 0; j < 4; j++) acc[nt][j] = fmaxf(acc[nt][j], 0.f);
    }
    if (LN) {
#pragma unroll
        for (int nt = 0; nt < 8; nt++) {
            float2 v0 = *(const float2*)(resid + (size_t)r0 * ldC + nt * 8 + 2 * gc);
            float2 v1 = *(const float2*)(resid + (size_t)r1 * ldC + nt * 8 + 2 * gc);
            acc[nt][0] += v0.x; acc[nt][1] += v0.y;
            acc[nt][2] += v1.x; acc[nt][3] += v1.y;
        }
        float s0 = 0.f, s1 = 0.f;
#pragma unroll
        for (int nt = 0; nt < 8; nt++) {
            s0 += acc[nt][0] + acc[nt][1];
            s1 += acc[nt][2] + acc[nt][3];
        }
        s0 += __shfl_xor_sync(0xffffffffu, s0, 1);
        s0 += __shfl_xor_sync(0xffffffffu, s0, 2);
        s1 += __shfl_xor_sync(0xffffffffu, s1, 1);
        s1 += __shfl_xor_sync(0xffffffffu, s1, 2);
        float mean0 = s0 * (1.f / HID), mean1 = s1 * (1.f / HID);
        float v0 = 0.f, v1 = 0.f;
#pragma unroll
        for (int nt = 0; nt < 8; nt++) {
            float d;
            d = acc[nt][0] - mean0; v0 += d * d;
            d = acc[nt][1] - mean0; v0 += d * d;
            d = acc[nt][2] - mean1; v1 += d * d;
            d = acc[nt][3] - mean1; v1 += d * d;
        }
        v0 += __shfl_xor_sync(0xffffffffu, v0, 1);
        v0 += __shfl_xor_sync(0xffffffffu, v0, 2);
        v1 += __shfl_xor_sync(0xffffffffu, v1, 1);
        v1 += __shfl_xor_sync(0xffffffffu, v1, 2);
        float rs0 = rsqrtf(v0 * (1.f / HID) + 1e-5f);
        float rs1 = rsqrtf(v1 * (1.f / HID) + 1e-5f);
#pragma unroll
        for (int nt = 0; nt < 8; nt++) {
            float g0 = __ldg(&gamma[nt * 8 + 2 * gc]);
            float g1 = __ldg(&gamma[nt * 8 + 2 * gc + 1]);
            float b0 = __ldg(&beta[nt * 8 + 2 * gc]);
            float b1 = __ldg(&beta[nt * 8 + 2 * gc + 1]);
            acc[nt][0] = (acc[nt][0] - mean0) * rs0 * g0 + b0;
            acc[nt][1] = (acc[nt][1] - mean0) * rs0 * g1 + b1;
            acc[nt][2] = (acc[nt][2] - mean1) * rs1 * g0 + b0;
            acc[nt][3] = (acc[nt][3] - mean1) * rs1 * g1 + b1;
        }
    }
#pragma unroll
    for (int nt = 0; nt < 8; nt++) {
        *(float2*)(C + (size_t)r0 * ldC + colC + nt * 8 + 2 * gc) =
            make_float2(acc[nt][0], acc[nt][1]);
        *(float2*)(C + (size_t)r1 * ldC + colC + nt * 8 + 2 * gc) =
            make_float2(acc[nt][2], acc[nt][3]);
    }
}

// ---------------- readout: gat_out into feat[:,0:15], copy obs into feat[:,15:1515] ----
__global__ void readout_kernel(const float* __restrict__ x, const int* __restrict__ agents,
                               const float* __restrict__ Wr, const float* __restrict__ br,
                               const float* __restrict__ obs, float* __restrict__ feat) {
    int row = blockIdx.x;
    __shared__ float sx[HID];
    int node = agents[row];
    if (threadIdx.x < HID) sx[threadIdx.x] = x[(size_t)node * HID + threadIdx.x];
    __syncthreads();
    if (threadIdx.x < AOUT) {
        float acc = br[threadIdx.x];
        for (int k = 0; k < HID; k++) acc += sx[k] * Wr[k * AOUT + threadIdx.x];
        feat[(size_t)row * FEATD + threadIdx.x] = acc;
    }
    for (int i = threadIdx.x; i < OBSD; i += blockDim.x)
        feat[(size_t)row * FEATD + AOUT + i] = obs[(size_t)row * OBSD + i];
}

// ---------------- small FC: one block per row ----------------
__global__ void fc_kernel(const float* __restrict__ in, int ldIn,
                          const float* __restrict__ W, const float* __restrict__ bias,
                          float* __restrict__ out, int ldOut,
                          int K, int N, int act /*1=tanh*/) {
    extern __shared__ float s_in[];
    int row = blockIdx.x;
    for (int i = threadIdx.x; i < K; i += blockDim.x)
        s_in[i] = in[(size_t)row * ldIn + i];
    __syncthreads();
    int n = threadIdx.x;
    if (n >= N) return;
    float acc = bias ? __ldg(&bias[n]) : 0.f;
    int k = 0;
    for (; k + 4 <= K; k += 4) {
        acc += s_in[k]     * W[(size_t)k       * N + n];
        acc += s_in[k + 1] * W[(size_t)(k + 1) * N + n];
        acc += s_in[k + 2] * W[(size_t)(k + 2) * N + n];
        acc += s_in[k + 3] * W[(size_t)(k + 3) * N + n];
    }
    for (; k < K; k++) acc += s_in[k] * W[(size_t)k * N + n];
    if (act) acc = tanhf(acc);
    out[(size_t)row * ldOut + n] = acc;
}

// ---------------- launch ----------------
extern "C" void kernel_launch(void* const* d_in, const int* in_sizes, int n_in,
                              void* d_out, int out_size) {
    const float* node_feats = (const float*)d_in[0];
    const float* obs        = (const float*)d_in[1];
    const int*   edge_src   = (const int*)d_in[2];
    const int*   edge_dst   = (const int*)d_in[3];
    const int*   agents     = (const int*)d_in[4];
    const float* W_in = (const float*)d_in[5];
    const float* Wq   = (const float*)d_in[6];
    const float* Wk   = (const float*)d_in[7];
    const float* Wv   = (const float*)d_in[8];
    const float* Wo   = (const float*)d_in[9];
    const float* ln1g = (const float*)d_in[10];
    const float* ln1b = (const float*)d_in[11];
    const float* W1   = (const float*)d_in[12];
    const float* b1   = (const float*)d_in[13];
    const float* W2   = (const float*)d_in[14];
    const float* b2   = (const float*)d_in[15];
    const float* ln2g = (const float*)d_in[16];
    const float* ln2b = (const float*)d_in[17];
    const float* Wr   = (const float*)d_in[18];
    const float* br   = (const float*)d_in[19];
    const float* Wp1  = (const float*)d_in[20];
    const float* bp1  = (const float*)d_in[21];
    const float* Wp2  = (const float*)d_in[22];
    const float* bp2  = (const float*)d_in[23];
    const float* Wlog = (const float*)d_in[24];
    const float* blog = (const float*)d_in[25];
    const float* Wv1  = (const float*)d_in[26];
    const float* bv1  = (const float*)d_in[27];
    const float* Wv2  = (const float*)d_in[28];
    const float* bv2  = (const float*)d_in[29];
    const float* Wvo  = (const float*)d_in[30];
    const float* bvo  = (const float*)d_in[31];
    float* out = (float*)d_out;

    float *x_p, *qkv_p, *agg_p, *h_p, *feat_p, *f1_p, *f2_p, *vh_p, *vh2_p, *whi, *wlo;
    int* cnt_p;
    cudaGetSymbolAddress((void**)&x_p,   g_x);
    cudaGetSymbolAddress((void**)&qkv_p, g_qkv);
    cudaGetSymbolAddress((void**)&agg_p, g_agg);
    cudaGetSymbolAddress((void**)&h_p,   g_h);
    cudaGetSymbolAddress((void**)&feat_p, g_feat);
    cudaGetSymbolAddress((void**)&f1_p,  g_f1);
    cudaGetSymbolAddress((void**)&f2_p,  g_f2);
    cudaGetSymbolAddress((void**)&vh_p,  g_vh);
    cudaGetSymbolAddress((void**)&vh2_p, g_vh2);
    cudaGetSymbolAddress((void**)&whi,   g_whi);
    cudaGetSymbolAddress((void**)&wlo,   g_wlo);
    cudaGetSymbolAddress((void**)&cnt_p, g_cnt);

    const int GX = TOT_N / 128;          // 1000 row-blocks

    // CSR build
    cudaMemsetAsync(cnt_p, 0, TOT_N * sizeof(int));
    count_kernel<<<(NEDGE + 255) / 256, 256>>>(edge_dst);
    scan_kernel<<<1, 1024>>>();
    cudaMemsetAsync(cnt_p, 0, TOT_N * sizeof(int));
    scatter_kernel<<<(NEDGE + 255) / 256, 256>>>(edge_src, edge_dst);

    // weight hi/lo splits (tf32)
    split_kernel<<<(SZ_WIN + 255) / 256, 256>>>(W_in, whi + OFF_WIN, wlo + OFF_WIN, SZ_WIN);
    split_kernel<<<(SZ_W  + 255) / 256, 256>>>(Wq,   whi + OFF_WQ,  wlo + OFF_WQ,  SZ_W);
    split_kernel<<<(SZ_W  + 255) / 256, 256>>>(Wk,   whi + OFF_WK,  wlo + OFF_WK,  SZ_W);
    split_kernel<<<(SZ_W  + 255) / 256, 256>>>(Wv,   whi + OFF_WV,  wlo + OFF_WV,  SZ_W);
    split_kernel<<<(SZ_W  + 255) / 256, 256>>>(Wo,   whi + OFF_WO,  wlo + OFF_WO,  SZ_W);
    split_kernel<<<(SZ_W1 + 255) / 256, 256>>>(W1,   whi + OFF_W1,  wlo + OFF_W1,  SZ_W1);
    split_kernel<<<(SZ_W2 + 255) / 256, 256>>>(W2,   whi + OFF_W2,  wlo + OFF_W2,  SZ_W2);

    // input projection: x = node_feats @ W_in   (K=32)
    gemmMMA<FIN, false, false, false, false><<<dim3(GX, 1), 256>>>(
        node_feats, whi + OFF_WIN, wlo + OFF_WIN, nullptr, nullptr, nullptr, nullptr,
        nullptr, nullptr, nullptr, nullptr, x_p, FIN, HID, HID);

    for (int l = 0; l < NLAYERS; l++) {
        size_t wOff  = (size_t)l * HID * HID;
        size_t w1Off = (size_t)l * HID * 2 * HID;
        size_t w2Off = (size_t)l * 2 * HID * HID;

        // fused qkv: [n,192] = x @ [Wq|Wk|Wv]
        gemmMMA<HID, false, false, true, false><<<dim3(GX, 3), 256>>>(
            x_p,
            whi + OFF_WQ + wOff, wlo + OFF_WQ + wOff,
            whi + OFF_WK + wOff, wlo + OFF_WK + wOff,
            whi + OFF_WV + wOff, wlo + OFF_WV + wOff,
            nullptr, nullptr, nullptr, nullptr, qkv_p, HID, HID, 3 * HID);

        attn_kernel<<<(TOT_N * NHEADS + 255) / 256, 256>>>(qkv_p, agg_p);

        // x = LN(x + agg @ Wo)   [fused epilogue]
        gemmMMA<HID, false, false, false, true><<<dim3(GX, 1), 256>>>(
            agg_p, whi + OFF_WO + wOff, wlo + OFF_WO + wOff,
            nullptr, nullptr, nullptr, nullptr,
            nullptr, x_p, ln1g + l * HID, ln1b + l * HID, x_p, HID, HID, HID);

        // h = relu(x @ W1 + b1)   [N=128 -> grid.y = 2]
        gemmMMA<HID, true, true, false, false><<<dim3(GX, 2), 256>>>(
            x_p, whi + OFF_W1 + w1Off, wlo + OFF_W1 + w1Off,
            nullptr, nullptr, nullptr, nullptr,
            b1 + (size_t)l * 2 * HID, nullptr, nullptr, nullptr,
            h_p, HID, 2 * HID, 2 * HID);

        // x = LN(x + h @ W2 + b2)   [fused epilogue]
        gemmMMA<2 * HID, false, true, false, true><<<dim3(GX, 1), 256>>>(
            h_p, whi + OFF_W2 + w2Off, wlo + OFF_W2 + w2Off,
            nullptr, nullptr, nullptr, nullptr,
            b2 + (size_t)l * HID, x_p, ln2g + l * HID, ln2b + l * HID,
            x_p, 2 * HID, HID, HID);
    }

    // readout + concat with obs
    readout_kernel<<<NB, 256>>>(x_p, agents, Wr, br, obs, feat_p);

    // policy head
    fc_kernel<<<NB, HSZ, FEATD * sizeof(float)>>>(feat_p, FEATD, Wp1, bp1, f1_p, HSZ, FEATD, HSZ, 1);
    fc_kernel<<<NB, HSZ, HSZ * sizeof(float)>>>(f1_p, HSZ, Wp2, bp2, f2_p, HSZ, HSZ, HSZ, 1);
    fc_kernel<<<NB, HSZ, HSZ * sizeof(float)>>>(f2_p, HSZ, Wlog, blog, out, AOUT, HSZ, AOUT, 0);

    // value head
    fc_kernel<<<NB, 256, OBSD * sizeof(float)>>>(obs, OBSD, Wv1, bv1, vh_p, VH, OBSD, VH, 1);
    fc_kernel<<<NB, VH, VH * sizeof(float)>>>(vh_p, VH, Wv2, bv2, vh2_p, VH, VH, VH, 1);
    fc_kernel<<<NB, 32, VH * sizeof(float)>>>(vh2_p, VH, Wvo, bvo, out + NB * AOUT, 1, VH, 1, 0);
}